// round 1
// baseline (speedup 1.0000x reference)
#include <cuda_runtime.h>
#include <cuda_bf16.h>
#include <cstdint>

// Problem dims (fixed instance)
#define T_STEPS 1024
#define BATCH   256
#define FDIM    512
#define MAXL    128   // max active indices per (t,b) row (mean ~51, 11 sigma margin)

// Fused-kernel tiling
#define GSL     64    // g-features per CTA (lane owns float2 -> 32 lanes cover 64)
#define NB      16    // batch elements per CTA (one warp each)
#define NSLICE  (FDIM / GSL)        // 8
#define NBGRP   (BATCH / NB)        // 16
#define NTHREADS (NB * 32)          // 512

// Scratch (static device allocations are the sanctioned scratch mechanism)
__device__ uint16_t g_lists[(size_t)T_STEPS * BATCH * MAXL]; // 64 MB
__device__ int      g_cnt[T_STEPS * BATCH];                  // 1 MB
__device__ float    g_Wt[FDIM * FDIM];                       // 1 MB, Wt[f][g] = W[g][f]

// ---------------------------------------------------------------------------
// Phase A1: transpose W (so a feature f's contribution is contiguous over g)
// ---------------------------------------------------------------------------
__global__ void transpose_kernel(const float* __restrict__ W) {
    __shared__ float tile[32][33];
    int bx = blockIdx.x * 32;  // f block
    int by = blockIdx.y * 32;  // g block
    int tx = threadIdx.x;
    for (int r = threadIdx.y; r < 32; r += 8)
        tile[r][tx] = W[(size_t)(by + r) * FDIM + bx + tx];
    __syncthreads();
    // Wt[bx+r][by+tx] = W[by+tx][bx+r] = tile[tx][r]
    for (int r = threadIdx.y; r < 32; r += 8)
        g_Wt[(size_t)(bx + r) * FDIM + by + tx] = tile[tx][r];
}

// ---------------------------------------------------------------------------
// Phase A2: compress binary spikes to sorted active-index lists (u16),
// padded with dummy index FDIM (a zero row in SMEM) to a multiple of 8.
// One warp per (t,b) row.
// ---------------------------------------------------------------------------
__global__ void compress_kernel(const float* __restrict__ spikes) {
    int warp_id = (blockIdx.x * blockDim.x + threadIdx.x) >> 5;
    int lane = threadIdx.x & 31;
    if (warp_id >= T_STEPS * BATCH) return;

    const float* row = spikes + (size_t)warp_id * FDIM;
    uint16_t* lst = g_lists + (size_t)warp_id * MAXL;

    int cnt = 0;
    #pragma unroll
    for (int c = 0; c < FDIM; c += 32) {
        float s = row[c + lane];
        unsigned m = __ballot_sync(0xFFFFFFFFu, s > 0.0f);
        if (s > 0.0f) {
            int pos = cnt + __popc(m & ((1u << lane) - 1u));
            if (pos < MAXL) lst[pos] = (uint16_t)(c + lane);
        }
        cnt += __popc(m);
    }
    if (cnt > MAXL - 8) cnt = MAXL - 8;        // safety clamp (never hit in practice)
    int padded = (cnt + 7) & ~7;
    if (lane < padded - cnt) lst[cnt + lane] = (uint16_t)FDIM;  // dummy -> zero row
    if (lane == 0) g_cnt[warp_id] = padded;
}

// ---------------------------------------------------------------------------
// Phase B: fused sparse-matvec + LIF scan.
// Grid: NSLICE * NBGRP = 128 CTAs. CTA caches Wt[:, g0:g0+64] (+1 zero row)
// in SMEM (131 KB). Warp w handles batch b = bgrp*NB + w across all 1024
// steps; lane owns 2 adjacent g features. State in registers, fp32 exact,
// rounding order pinned to the reference.
// ---------------------------------------------------------------------------
__global__ void __launch_bounds__(NTHREADS, 1)
lif_fused_kernel(float* __restrict__ out) {
    extern __shared__ float Wsm[];  // (FDIM+1) rows x GSL floats

    const int gsl  = blockIdx.x & (NSLICE - 1);
    const int bgrp = blockIdx.x >> 3;            // NSLICE == 8
    const int g0   = gsl * GSL;
    const int tid  = threadIdx.x;

    // Cooperative load of the W-transpose slice (coalesced 256B rows)
    for (int idx = tid; idx < FDIM * GSL; idx += NTHREADS) {
        int f = idx >> 6;         // GSL == 64
        int gl = idx & (GSL - 1);
        Wsm[f * GSL + gl] = g_Wt[(size_t)f * FDIM + g0 + gl];
    }
    for (int idx = tid; idx < GSL; idx += NTHREADS)
        Wsm[FDIM * GSL + idx] = 0.0f;            // zero row for padded indices
    __syncthreads();

    const int w = tid >> 5;
    const int lane = tid & 31;
    const int b = bgrp * NB + w;
    const float* wrow = Wsm + lane * 2;

    float vx = 0.0f, vy = 0.0f;   // membrane
    float ix = 0.0f, iy = 0.0f;   // synaptic current
    float zx = 0.0f, zy = 0.0f;   // last spike

    for (int t = 0; t < T_STEPS; t++) {
        const int r = t * BATCH + b;
        const int cnt = g_cnt[r];
        const uint16_t* lst = g_lists + (size_t)r * MAXL;

        // x[b, g:g+1] = sum over active f of Wt[f][g], ascending f order
        float xx = 0.0f, xy = 0.0f;
        for (int j = 0; j < cnt; j += 32) {
            int myf = lst[j + lane];             // in-bounds: j+lane < MAXL
            int lim = min(32, cnt - j);          // multiple of 8
            for (int k = 0; k < lim; k += 8) {
                #pragma unroll
                for (int u = 0; u < 8; u++) {
                    int f = __shfl_sync(0xFFFFFFFFu, myf, k + u);
                    float2 wv = *(const float2*)(wrow + f * GSL);
                    xx += wv.x;
                    xy += wv.y;
                }
            }
        }

        // LIF update, exact fp32 in reference op order:
        // v_dec = v + 0.1*((0 - v) + i); i_dec = i - 0.2*i
        float vdx = __fadd_rn(vx, __fmul_rn(0.1f, __fadd_rn(-vx, ix)));
        float vdy = __fadd_rn(vy, __fmul_rn(0.1f, __fadd_rn(-vy, iy)));
        float idx_ = __fadd_rn(ix, -__fmul_rn(0.2f, ix));
        float idy_ = __fadd_rn(iy, -__fmul_rn(0.2f, iy));
        bool sx = vdx > 1.0f;
        bool sy = vdy > 1.0f;
        zx = sx ? 1.0f : 0.0f;
        zy = sy ? 1.0f : 0.0f;
        vx = sx ? 0.0f : vdx;
        vy = sy ? 0.0f : vdy;
        ix = __fadd_rn(idx_, xx);
        iy = __fadd_rn(idy_, xy);
    }

    // Outputs: concat(z_last[B,F], v[B,F], i[B,F])
    const int gg = g0 + lane * 2;
    const size_t base = (size_t)b * FDIM + gg;
    float2* oz = (float2*)(out + base);
    float2* ov = (float2*)(out + (size_t)BATCH * FDIM + base);
    float2* oi = (float2*)(out + 2 * (size_t)BATCH * FDIM + base);
    *oz = make_float2(zx, zy);
    *ov = make_float2(vx, vy);
    *oi = make_float2(ix, iy);
}

// ---------------------------------------------------------------------------
extern "C" void kernel_launch(void* const* d_in, const int* in_sizes, int n_in,
                              void* d_out, int out_size) {
    const float* spikes = (const float*)d_in[0];  // [T, B, F] fp32 (binary)
    const float* W      = (const float*)d_in[1];  // [F, F] fp32
    float* out          = (float*)d_out;          // [3, B, F] fp32

    (void)in_sizes; (void)n_in; (void)out_size;

    // SMEM: (512+1) rows * 64 floats * 4B = 131328 B > 48KB default
    cudaFuncSetAttribute(lif_fused_kernel,
                         cudaFuncAttributeMaxDynamicSharedMemorySize,
                         (FDIM + 1) * GSL * (int)sizeof(float));

    transpose_kernel<<<dim3(FDIM / 32, FDIM / 32), dim3(32, 8)>>>(W);
    compress_kernel<<<(T_STEPS * BATCH) / 8, 256>>>(spikes);
    lif_fused_kernel<<<NSLICE * NBGRP, NTHREADS,
                       (FDIM + 1) * GSL * (int)sizeof(float)>>>(out);
}

// round 2
// speedup vs baseline: 1.4973x; 1.4973x over previous
#include <cuda_runtime.h>
#include <cuda_bf16.h>
#include <cstdint>

// Problem dims (fixed instance)
#define T_STEPS 1024
#define BATCH   256
#define FDIM    512
#define MAXL    128   // max active indices per (t,b) row (mean ~51)

// Fused-kernel tiling
#define GSL     64    // g-features per CTA (lane owns float2 -> 32 lanes cover 64)
#define NB      16    // batch elements per CTA (one warp each)
#define NSLICE  (FDIM / GSL)        // 8
#define NBGRP   (BATCH / NB)        // 16
#define NTHREADS (NB * 32)          // 512

// Scratch (static device arrays are the sanctioned scratch mechanism).
// +64 entries of slack so depth-3 uint4 prefetch can overread the tail row.
__device__ uint16_t g_lists[(size_t)T_STEPS * BATCH * MAXL + 64];
__device__ int      g_cnt[T_STEPS * BATCH];
__device__ float    g_Wt[FDIM * FDIM];   // Wt[f][g] = W[g][f]

// ---------------------------------------------------------------------------
// Phase A1: transpose W (feature f's row contiguous over g)
// ---------------------------------------------------------------------------
__global__ void transpose_kernel(const float* __restrict__ W) {
    __shared__ float tile[32][33];
    int bx = blockIdx.x * 32;  // f block
    int by = blockIdx.y * 32;  // g block
    int tx = threadIdx.x;
    for (int r = threadIdx.y; r < 32; r += 8)
        tile[r][tx] = W[(size_t)(by + r) * FDIM + bx + tx];
    __syncthreads();
    for (int r = threadIdx.y; r < 32; r += 8)
        g_Wt[(size_t)(bx + r) * FDIM + by + tx] = tile[tx][r];
}

// ---------------------------------------------------------------------------
// Phase A2: compress binary spikes to sorted active-index lists (u16),
// padded with dummy index FDIM (zero row in SMEM) to a multiple of 8.
// One warp per (t,b) row.
// ---------------------------------------------------------------------------
__global__ void compress_kernel(const float* __restrict__ spikes) {
    int warp_id = (blockIdx.x * blockDim.x + threadIdx.x) >> 5;
    int lane = threadIdx.x & 31;
    if (warp_id >= T_STEPS * BATCH) return;

    const float* row = spikes + (size_t)warp_id * FDIM;
    uint16_t* lst = g_lists + (size_t)warp_id * MAXL;

    int cnt = 0;
    #pragma unroll
    for (int c = 0; c < FDIM; c += 32) {
        float s = row[c + lane];
        unsigned m = __ballot_sync(0xFFFFFFFFu, s > 0.0f);
        if (s > 0.0f) {
            int pos = cnt + __popc(m & ((1u << lane) - 1u));
            if (pos < MAXL) lst[pos] = (uint16_t)(c + lane);
        }
        cnt += __popc(m);
    }
    if (cnt > MAXL - 8) cnt = MAXL - 8;        // safety clamp (stat. never hit)
    int padded = (cnt + 7) & ~7;
    if (lane < padded - cnt) lst[cnt + lane] = (uint16_t)FDIM;  // dummy -> zero row
    if (lane == 0) g_cnt[warp_id] = padded;
}

// ---------------------------------------------------------------------------
// Phase B: fused sparse-matvec + LIF scan.
// 128 CTAs = 8 g-slices x 16 batch-groups. CTA caches Wt[:, g0:g0+64] (+ zero
// row) in 131 KB SMEM. Warp = one batch element; lane owns a float2 of g.
// Indices arrive as warp-uniform uint4 broadcasts (no shfl); weight rows via
// conflict-free LDS.64; accumulation via packed add.rn.f32x2 (fp32-exact).
// ---------------------------------------------------------------------------
__global__ void __launch_bounds__(NTHREADS, 1)
lif_fused_kernel(float* __restrict__ out) {
    extern __shared__ float Wsm[];  // (FDIM+1) rows x GSL floats

    const int gsl  = blockIdx.x & (NSLICE - 1);
    const int bgrp = blockIdx.x >> 3;            // NSLICE == 8
    const int g0   = gsl * GSL;
    const int tid  = threadIdx.x;

    // Cooperative load of the W-transpose slice (coalesced 256B rows)
    for (int idx = tid; idx < FDIM * GSL; idx += NTHREADS) {
        int f = idx >> 6;
        int gl = idx & (GSL - 1);
        Wsm[f * GSL + gl] = g_Wt[(size_t)f * FDIM + g0 + gl];
    }
    for (int idx = tid; idx < GSL; idx += NTHREADS)
        Wsm[FDIM * GSL + idx] = 0.0f;            // zero row for padded indices
    __syncthreads();

    const int w = tid >> 5;
    const int lane = tid & 31;
    const int b = bgrp * NB + w;

    // smem base address for this lane's float2 column (generic -> shared u32)
    uint32_t wbase;
    {
        uint64_t gp = (uint64_t)(Wsm + lane * 2);
        asm("{ .reg .u64 t; cvta.to.shared.u64 t, %1; cvt.u32.u64 %0, t; }"
            : "=r"(wbase) : "l"(gp));
    }

    float vx = 0.0f, vy = 0.0f;   // membrane
    float ix = 0.0f, iy = 0.0f;   // synaptic current
    float zx = 0.0f, zy = 0.0f;   // last spike

    // Prefetch row t=0 metadata
    int r = b;
    int cnt = g_cnt[r];
    const uint4* wp = (const uint4*)(g_lists + (size_t)r * MAXL);
    uint4 q0 = wp[0], q1 = wp[1], q2 = wp[2];

    for (int t = 0; t < T_STEPS; t++) {
        // Prefetch NEXT row's count + head words (hides L2 latency under work)
        const int rn = (t < T_STEPS - 1) ? r + BATCH : r;
        const int cntn = g_cnt[rn];
        const uint4* wpn = (const uint4*)(g_lists + (size_t)rn * MAXL);
        const uint4 p0 = wpn[0], p1 = wpn[1], p2 = wpn[2];

        uint64_t acc0 = 0ULL, acc1 = 0ULL;       // packed f32x2 accumulators
        const int nwords = cnt >> 3;             // cnt is a multiple of 8

        #define PROC_PAIR(a)                                                     \
        {                                                                        \
            uint32_t f0_ = (a) & 0xFFFFu;                                        \
            uint32_t f1_ = (a) >> 16;                                            \
            uint64_t w0_, w1_;                                                   \
            asm volatile("ld.shared.b64 %0, [%1];"                               \
                         : "=l"(w0_) : "r"(wbase + (f0_ << 8)));                 \
            asm volatile("ld.shared.b64 %0, [%1];"                               \
                         : "=l"(w1_) : "r"(wbase + (f1_ << 8)));                 \
            asm volatile("add.rn.f32x2 %0, %1, %2;"                              \
                         : "=l"(acc0) : "l"(acc0), "l"(w0_));                    \
            asm volatile("add.rn.f32x2 %0, %1, %2;"                              \
                         : "=l"(acc1) : "l"(acc1), "l"(w1_));                    \
        }

        for (int k = 0; k < nwords; k++) {
            uint4 qn = wp[k + 3];                // depth-3 in-row prefetch
            PROC_PAIR(q0.x); PROC_PAIR(q0.y); PROC_PAIR(q0.z); PROC_PAIR(q0.w);
            q0 = q1; q1 = q2; q2 = qn;
        }
        #undef PROC_PAIR

        // combine chains, unpack packed accumulator
        uint64_t accp;
        asm("add.rn.f32x2 %0, %1, %2;" : "=l"(accp) : "l"(acc0), "l"(acc1));
        uint32_t xlo, xhi;
        asm("mov.b64 {%0, %1}, %2;" : "=r"(xlo), "=r"(xhi) : "l"(accp));
        const float xx = __uint_as_float(xlo);
        const float xy = __uint_as_float(xhi);

        // LIF update, exact fp32 in reference op order
        float vdx = __fadd_rn(vx, __fmul_rn(0.1f, __fadd_rn(-vx, ix)));
        float vdy = __fadd_rn(vy, __fmul_rn(0.1f, __fadd_rn(-vy, iy)));
        float idx_ = __fadd_rn(ix, -__fmul_rn(0.2f, ix));
        float idy_ = __fadd_rn(iy, -__fmul_rn(0.2f, iy));
        bool sx = vdx > 1.0f;
        bool sy = vdy > 1.0f;
        zx = sx ? 1.0f : 0.0f;
        zy = sy ? 1.0f : 0.0f;
        vx = sx ? 0.0f : vdx;
        vy = sy ? 0.0f : vdy;
        ix = __fadd_rn(idx_, xx);
        iy = __fadd_rn(idy_, xy);

        // rotate prefetched next-row state in
        r = rn; cnt = cntn; wp = wpn;
        q0 = p0; q1 = p1; q2 = p2;
    }

    // Outputs: concat(z_last[B,F], v[B,F], i[B,F])
    const int gg = g0 + lane * 2;
    const size_t base = (size_t)b * FDIM + gg;
    *(float2*)(out + base)                            = make_float2(zx, zy);
    *(float2*)(out + (size_t)BATCH * FDIM + base)     = make_float2(vx, vy);
    *(float2*)(out + 2 * (size_t)BATCH * FDIM + base) = make_float2(ix, iy);
}

// ---------------------------------------------------------------------------
extern "C" void kernel_launch(void* const* d_in, const int* in_sizes, int n_in,
                              void* d_out, int out_size) {
    const float* spikes = (const float*)d_in[0];  // [T, B, F] fp32 (binary)
    const float* W      = (const float*)d_in[1];  // [F, F] fp32
    float* out          = (float*)d_out;          // [3, B, F] fp32

    (void)in_sizes; (void)n_in; (void)out_size;

    cudaFuncSetAttribute(lif_fused_kernel,
                         cudaFuncAttributeMaxDynamicSharedMemorySize,
                         (FDIM + 1) * GSL * (int)sizeof(float));

    transpose_kernel<<<dim3(FDIM / 32, FDIM / 32), dim3(32, 8)>>>(W);
    compress_kernel<<<(T_STEPS * BATCH) / 8, 256>>>(spikes);
    lif_fused_kernel<<<NSLICE * NBGRP, NTHREADS,
                       (FDIM + 1) * GSL * (int)sizeof(float)>>>(out);
}